// round 11
// baseline (speedup 1.0000x reference)
#include <cuda_runtime.h>
#include <cstdint>

#define CHAR_EMB 30
#define NFILT    30
#define MAXW     40
#define NCHARS   102
#define TH       256          // 8 warps/block, one position per warp
#define NW       (TH / 32)

typedef unsigned long long ull;

union F2U { float2 f; ull u; };

__device__ __forceinline__ ull pk2(float lo, float hi) {
    F2U v; v.f = make_float2(lo, hi); return v.u;
}
__device__ __forceinline__ float2 upk2(ull x) {
    F2U v; v.u = x; return v.f;
}
__device__ __forceinline__ ull fma2(ull a, ull b, ull c) {
    ull d;
    asm("fma.rn.f32x2 %0, %1, %2, %3;" : "=l"(d) : "l"(a), "l"(b), "l"(c));
    return d;
}
__device__ __forceinline__ ull mul2(ull a, ull b) {
    ull d;
    asm("mul.rn.f32x2 %0, %1, %2;" : "=l"(d) : "l"(a), "l"(b));
    return d;
}

// Warp-autonomous persistent encoder; two time-passes merged through the
// per-warp smem stage buffer (halved x registers -> 6 warps/SMSP), with
// conflict-free weight tables and coalesced bias-add stores.
__global__ __launch_bounds__(TH, 3)
void encoder_kernel(const int*    __restrict__ char_ids,
                    const int*    __restrict__ word_ids,
                    const float*  __restrict__ char_emb,
                    const float*  __restrict__ conv_w,
                    const float*  __restrict__ conv_b,
                    const float4* __restrict__ glove4,
                    float*        __restrict__ out,
                    int n_pos)
{
    __shared__ float      emb_s[NCHARS * CHAR_EMB];  // [char][e]
    __shared__ ulonglong2 wsA[900];                  // [f*30+e] = {w0pair, w1pair}
    __shared__ float      wsW2[900];                 // [f*30+e] = w2
    __shared__ float      stg[NW][900];              // per-warp output stage

    const int tid  = threadIdx.x;
    const int lane = tid & 31;
    const int wrp  = tid >> 5;

    for (int i = tid; i < NCHARS * CHAR_EMB; i += TH)
        emb_s[i] = char_emb[i];
    for (int oc = tid; oc < 900; oc += TH) {
        const int e = oc / NFILT, f = oc % NFILT;
        const float* wp = conv_w + (size_t)oc * 3;
        ulonglong2 a;
        a.x = pk2(wp[0], wp[0]);
        a.y = pk2(wp[1], wp[1]);
        wsA[f * 30 + e]  = a;
        wsW2[f * 30 + e] = wp[2];
    }
    __syncthreads();

    const int el = (lane < CHAR_EMB) ? lane : CHAR_EMB - 1;  // safe column
    float* stg_w = stg[wrp];

    const int wstride = gridDim.x * NW;
    int p = blockIdx.x * NW + wrp;
    if (p >= n_pos) return;

    int2 c = make_int2(0, 0);
    if (lane < 20) c = reinterpret_cast<const int2*>(char_ids)[(size_t)p * 20 + lane];

    while (true) {
        const int pn = p + wstride;
        int2 cn = make_int2(0, 0);
        if (pn < n_pos && lane < 20)
            cn = reinterpret_cast<const int2*>(char_ids)[(size_t)pn * 20 + lane];

        // glove gather (independent memory work)
        if (lane < 25) {
            const int wid = word_ids[p];
            reinterpret_cast<float4*>(out)[(size_t)p * 250 + 225 + lane] =
                glove4[(size_t)wid * 25 + lane];
        }

#define EV(t) emb_s[__shfl_sync(0xFFFFFFFFu, (((t) & 1) ? c.y : c.x), (t) >> 1) * CHAR_EMB + el]

        // ============ PASS A: y[0..19] from x[0..21] ============
        {
            ull xe[11], xo[10];
            float x0 = EV(0);
            float x1 = EV(1);
            xe[0] = pk2(x0, x1);
#pragma unroll
            for (int i = 1; i < 11; i++) {
                float x2 = EV(2 * i);
                float x3 = EV(2 * i + 1);
                xe[i]     = pk2(x2, x3);
                xo[i - 1] = pk2(x1, x2);
                x1 = x3;
            }
            if (lane < CHAR_EMB) {
#pragma unroll 2
                for (int f = 0; f < NFILT; f++) {
                    const ulonglong2 wa = wsA[f * 30 + lane];
                    const float      w2 = wsW2[f * 30 + lane];
                    const ull w2p = pk2(w2, w2);
                    float m0 = -3.402823466e+38f, m1 = m0;
#pragma unroll
                    for (int i = 0; i < 10; i++) {
                        ull acc = mul2(w2p, xe[i + 1]);
                        acc = fma2(wa.y, xo[i], acc);
                        acc = fma2(wa.x, xe[i], acc);
                        const float2 y = upk2(acc);
                        m0 = fmaxf(m0, y.x);
                        m1 = fmaxf(m1, y.y);
                    }
                    stg_w[lane * 30 + f] = fmaxf(m0, m1);   // raw partial
                }
            }
        }

        // ============ PASS B: y[18..37] from x[18..39], merge in smem ====
        {
            ull xe[11], xo[10];
            float x0 = EV(18);
            float x1 = EV(19);
            xe[0] = pk2(x0, x1);
#pragma unroll
            for (int i = 1; i < 11; i++) {
                float x2 = EV(18 + 2 * i);
                float x3 = EV(19 + 2 * i);
                xe[i]     = pk2(x2, x3);
                xo[i - 1] = pk2(x1, x2);
                x1 = x3;
            }
            if (lane < CHAR_EMB) {
#pragma unroll 2
                for (int f = 0; f < NFILT; f++) {
                    const ulonglong2 wa = wsA[f * 30 + lane];
                    const float      w2 = wsW2[f * 30 + lane];
                    const ull w2p = pk2(w2, w2);
                    float m0 = -3.402823466e+38f, m1 = m0;
#pragma unroll
                    for (int i = 0; i < 10; i++) {
                        ull acc = mul2(w2p, xe[i + 1]);
                        acc = fma2(wa.y, xo[i], acc);
                        acc = fma2(wa.x, xe[i], acc);
                        const float2 y = upk2(acc);
                        m0 = fmaxf(m0, y.x);
                        m1 = fmaxf(m1, y.y);
                    }
                    const float prev = stg_w[lane * 30 + f];  // same thread
                    stg_w[lane * 30 + f] = fmaxf(prev, fmaxf(m0, m1));
                }
            }
        }
#undef EV
        __syncwarp();

        // ---- coalesced store: 900 floats as float4, bias added here ----
        {
            float* outp = out + (size_t)p * 1000;
#pragma unroll
            for (int it = 0; it < 8; it++) {
                const int j4 = it * 32 + lane;          // float4 index, 225 total
                if (j4 < 225) {
                    const float4 v = reinterpret_cast<const float4*>(stg_w)[j4];
                    const float4 b = __ldg(reinterpret_cast<const float4*>(conv_b) + j4);
                    float4 r;
                    r.x = v.x + b.x; r.y = v.y + b.y;
                    r.z = v.z + b.z; r.w = v.w + b.w;
                    reinterpret_cast<float4*>(outp)[j4] = r;
                }
            }
        }
        __syncwarp();

        if (pn >= n_pos) break;
        p = pn;
        c = cn;
    }
}

extern "C" void kernel_launch(void* const* d_in, const int* in_sizes, int n_in,
                              void* d_out, int out_size)
{
    const int*   char_ids = (const int*)d_in[0];
    const int*   word_ids = (const int*)d_in[1];
    const float* char_emb = (const float*)d_in[2];
    const float* conv_w   = (const float*)d_in[3];
    const float* conv_b   = (const float*)d_in[4];
    const float* glove    = (const float*)d_in[5];
    float*       out      = (float*)d_out;

    const int n_pos = in_sizes[1];   // B*S

    int blocks = 444;                // 3 resident blocks/SM on 148 SMs
    if (blocks * NW > n_pos) blocks = (n_pos + NW - 1) / NW;
    encoder_kernel<<<blocks, TH>>>(char_ids, word_ids, char_emb, conv_w, conv_b,
                                   (const float4*)glove, out, n_pos);
}

// round 12
// speedup vs baseline: 1.1218x; 1.1218x over previous
#include <cuda_runtime.h>
#include <cstdint>

#define CHAR_EMB 30
#define NFILT    30
#define MAXW     40
#define NCHARS   102
#define TH       128          // 4 warps/block, one position per warp

typedef unsigned long long ull;

union F2U { float2 f; ull u; };

__device__ __forceinline__ ull pk2(float lo, float hi) {
    F2U v; v.f = make_float2(lo, hi); return v.u;
}
__device__ __forceinline__ float2 upk2(ull x) {
    F2U v; v.u = x; return v.f;
}
__device__ __forceinline__ ull fma2(ull a, ull b, ull c) {
    ull d;
    asm("fma.rn.f32x2 %0, %1, %2, %3;" : "=l"(d) : "l"(a), "l"(b), "l"(c));
    return d;
}
__device__ __forceinline__ ull mul2(ull a, ull b) {
    ull d;
    asm("mul.rn.f32x2 %0, %1, %2;" : "=l"(d) : "l"(a), "l"(b));
    return d;
}

// R10 core (warp-autonomous, register-resident x, conflict-free weight
// tables, smem-staged coalesced stores) with the per-filter max chains split
// into 4 independent accumulators (depth 19 -> 10) for 2x per-warp ILP.
__global__ __launch_bounds__(TH, 4)
void encoder_kernel(const int*    __restrict__ char_ids,
                    const int*    __restrict__ word_ids,
                    const float*  __restrict__ char_emb,
                    const float*  __restrict__ conv_w,
                    const float*  __restrict__ conv_b,
                    const float4* __restrict__ glove4,
                    float*        __restrict__ out,
                    int n_pos)
{
    __shared__ float      emb_s[NCHARS * CHAR_EMB];  // [char][e]
    __shared__ ulonglong2 wsA[900];                  // [f*30+e] = {w0pair, w1pair}
    __shared__ float      wsW2[900];                 // [f*30+e] = w2
    __shared__ float      stg[4][900];               // per-warp output stage

    const int tid  = threadIdx.x;
    const int lane = tid & 31;
    const int wrp  = tid >> 5;

    for (int i = tid; i < NCHARS * CHAR_EMB; i += TH)
        emb_s[i] = char_emb[i];
    for (int oc = tid; oc < 900; oc += TH) {
        const int e = oc / NFILT, f = oc % NFILT;
        const float* wp = conv_w + (size_t)oc * 3;
        ulonglong2 a;
        a.x = pk2(wp[0], wp[0]);
        a.y = pk2(wp[1], wp[1]);
        wsA[f * 30 + e]  = a;
        wsW2[f * 30 + e] = wp[2];
    }
    __syncthreads();

    const int el = (lane < CHAR_EMB) ? lane : CHAR_EMB - 1;  // safe column
    float* stg_w = stg[wrp];

    const int wstride = gridDim.x * (TH / 32);
    int p = blockIdx.x * (TH / 32) + wrp;
    if (p >= n_pos) return;

    int2 c = make_int2(0, 0);
    if (lane < 20) c = reinterpret_cast<const int2*>(char_ids)[(size_t)p * 20 + lane];

    while (true) {
        const int pn = p + wstride;
        int2 cn = make_int2(0, 0);
        if (pn < n_pos && lane < 20)
            cn = reinterpret_cast<const int2*>(char_ids)[(size_t)pn * 20 + lane];

        // glove gather (independent)
        if (lane < 25) {
            const int wid = word_ids[p];
            reinterpret_cast<float4*>(out)[(size_t)p * 250 + 225 + lane] =
                glove4[(size_t)wid * 25 + lane];
        }

        // ---- gather + pack x[e = lane, 0..39] into both conv phases ----
        ull xe[20], xo[19];
        {
#define EV(t) emb_s[__shfl_sync(0xFFFFFFFFu, (((t) & 1) ? c.y : c.x), (t) >> 1) * CHAR_EMB + el]
            float x0 = EV(0);
            float x1 = EV(1);
            xe[0] = pk2(x0, x1);
#pragma unroll
            for (int i = 1; i < 20; i++) {
                float x2 = EV(2 * i);
                float x3 = EV(2 * i + 1);
                xe[i]     = pk2(x2, x3);
                xo[i - 1] = pk2(x1, x2);
                x1 = x3;
            }
#undef EV
        }

        // ---- 30 filters; 4 independent max chains per filter ----
        if (lane < CHAR_EMB) {
#pragma unroll 2
            for (int f = 0; f < NFILT; f++) {
                const ulonglong2 wa = wsA[f * 30 + lane];      // {w0, w1}
                const float      w2 = wsW2[f * 30 + lane];
                const ull w2p = pk2(w2, w2);
                float m0a = -3.402823466e+38f, m1a = m0a;
                float m0b = m0a, m1b = m0a;
#pragma unroll
                for (int i = 0; i < 10; i++) {
                    // stream A: y[2i], y[2i+1]
                    {
                        ull acc = mul2(w2p, xe[i + 1]);
                        acc = fma2(wa.y, xo[i], acc);
                        acc = fma2(wa.x, xe[i], acc);
                        const float2 y = upk2(acc);
                        m0a = fmaxf(m0a, y.x);
                        m1a = fmaxf(m1a, y.y);
                    }
                    // stream B: y[2(i+10)], y[2(i+10)+1]  (9 iterations)
                    if (i < 9) {
                        ull acc = mul2(w2p, xe[i + 11]);
                        acc = fma2(wa.y, xo[i + 10], acc);
                        acc = fma2(wa.x, xe[i + 10], acc);
                        const float2 y = upk2(acc);
                        m0b = fmaxf(m0b, y.x);
                        m1b = fmaxf(m1b, y.y);
                    }
                }
                stg_w[lane * 30 + f] =
                    fmaxf(fmaxf(m0a, m1a), fmaxf(m0b, m1b));
            }
        }
        __syncwarp();

        // ---- coalesced store: 900 floats as float4, bias added here ----
        {
            float* outp = out + (size_t)p * 1000;
#pragma unroll
            for (int it = 0; it < 8; it++) {
                const int j4 = it * 32 + lane;          // float4 index, 225 total
                if (j4 < 225) {
                    const float4 v = reinterpret_cast<const float4*>(stg_w)[j4];
                    const float4 b = __ldg(reinterpret_cast<const float4*>(conv_b) + j4);
                    float4 r;
                    r.x = v.x + b.x; r.y = v.y + b.y;
                    r.z = v.z + b.z; r.w = v.w + b.w;
                    reinterpret_cast<float4*>(outp)[j4] = r;
                }
            }
        }
        __syncwarp();

        if (pn >= n_pos) break;
        p = pn;
        c = cn;
    }
}

extern "C" void kernel_launch(void* const* d_in, const int* in_sizes, int n_in,
                              void* d_out, int out_size)
{
    const int*   char_ids = (const int*)d_in[0];
    const int*   word_ids = (const int*)d_in[1];
    const float* char_emb = (const float*)d_in[2];
    const float* conv_w   = (const float*)d_in[3];
    const float* conv_b   = (const float*)d_in[4];
    const float* glove    = (const float*)d_in[5];
    float*       out      = (float*)d_out;

    const int n_pos = in_sizes[1];   // B*S

    int blocks = 592;                // 4 resident blocks/SM on 148 SMs
    if (blocks * (TH / 32) > n_pos) blocks = (n_pos + TH / 32 - 1) / (TH / 32);
    encoder_kernel<<<blocks, TH>>>(char_ids, word_ids, char_emb, conv_w, conv_b,
                                   (const float4*)glove, out, n_pos);
}

// round 14
// speedup vs baseline: 1.1410x; 1.0171x over previous
#include <cuda_runtime.h>
#include <cstdint>

#define CHAR_EMB 30
#define NFILT    30
#define MAXW     40
#define NCHARS   102
#define TH       128          // 4 warps/block, one position per warp

typedef unsigned long long ull;

union F2U { float2 f; ull u; };

__device__ __forceinline__ ull pk2(float lo, float hi) {
    F2U v; v.f = make_float2(lo, hi); return v.u;
}
__device__ __forceinline__ float2 upk2(ull x) {
    F2U v; v.u = x; return v.f;
}
__device__ __forceinline__ ull fma2(ull a, ull b, ull c) {
    ull d;
    asm("fma.rn.f32x2 %0, %1, %2, %3;" : "=l"(d) : "l"(a), "l"(b), "l"(c));
    return d;
}
__device__ __forceinline__ ull mul2(ull a, ull b) {
    ull d;
    asm("mul.rn.f32x2 %0, %1, %2;" : "=l"(d) : "l"(a), "l"(b));
    return d;
}

// R12 skeleton + glove LDG/STG split around the filter loop (hides random
// DRAM latency) + explicit weight register pipeline (LDS never heads a
// filter's dependency chain). Scalar fmax, 4 independent chains per filter.
__global__ __launch_bounds__(TH, 4)
void encoder_kernel(const int*    __restrict__ char_ids,
                    const int*    __restrict__ word_ids,
                    const float*  __restrict__ char_emb,
                    const float*  __restrict__ conv_w,
                    const float*  __restrict__ conv_b,
                    const float4* __restrict__ glove4,
                    float*        __restrict__ out,
                    int n_pos)
{
    __shared__ float      emb_s[NCHARS * CHAR_EMB];  // [char][e]
    __shared__ ulonglong2 wsA[900];                  // [f*30+e] = {w0pair, w1pair}
    __shared__ float      wsW2[900];                 // [f*30+e] = w2
    __shared__ float      stg[4][900];               // per-warp output stage

    const int tid  = threadIdx.x;
    const int lane = tid & 31;
    const int wrp  = tid >> 5;

    for (int i = tid; i < NCHARS * CHAR_EMB; i += TH)
        emb_s[i] = char_emb[i];
    for (int oc = tid; oc < 900; oc += TH) {
        const int e = oc / NFILT, f = oc % NFILT;
        const float* wp = conv_w + (size_t)oc * 3;
        ulonglong2 a;
        a.x = pk2(wp[0], wp[0]);
        a.y = pk2(wp[1], wp[1]);
        wsA[f * 30 + e]  = a;
        wsW2[f * 30 + e] = wp[2];
    }
    __syncthreads();

    const int el = (lane < CHAR_EMB) ? lane : CHAR_EMB - 1;  // safe column
    float* stg_w = stg[wrp];

    const int wstride = gridDim.x * (TH / 32);
    int p = blockIdx.x * (TH / 32) + wrp;
    if (p >= n_pos) return;

    int2 c = make_int2(0, 0);
    if (lane < 20) c = reinterpret_cast<const int2*>(char_ids)[(size_t)p * 20 + lane];

    while (true) {
        const int pn = p + wstride;
        int2 cn = make_int2(0, 0);
        if (pn < n_pos && lane < 20)
            cn = reinterpret_cast<const int2*>(char_ids)[(size_t)pn * 20 + lane];

        // glove: issue the random-DRAM load NOW, store after the filter loop
        float4 gval = make_float4(0.f, 0.f, 0.f, 0.f);
        if (lane < 25) {
            const int wid = word_ids[p];
            gval = __ldg(glove4 + (size_t)wid * 25 + lane);
        }

        // ---- gather + pack x[e = lane, 0..39] into both conv phases ----
        ull xe[20], xo[19];
        {
#define EV(t) emb_s[__shfl_sync(0xFFFFFFFFu, (((t) & 1) ? c.y : c.x), (t) >> 1) * CHAR_EMB + el]
            float x0 = EV(0);
            float x1 = EV(1);
            xe[0] = pk2(x0, x1);
#pragma unroll
            for (int i = 1; i < 20; i++) {
                float x2 = EV(2 * i);
                float x3 = EV(2 * i + 1);
                xe[i]     = pk2(x2, x3);
                xo[i - 1] = pk2(x1, x2);
                x1 = x3;
            }
#undef EV
        }

        // ---- 30 filters; 4 max chains; weight register pipeline ----
        if (lane < CHAR_EMB) {
            ulonglong2 wa = wsA[lane];           // filter 0 weights
            float      w2 = wsW2[lane];
#pragma unroll 2
            for (int f = 0; f < NFILT; f++) {
                // prefetch next filter's weights (issued before the math)
                const int fn = (f < NFILT - 1) ? f + 1 : f;
                const ulonglong2 wan = wsA[fn * 30 + lane];
                const float      w2n = wsW2[fn * 30 + lane];

                const ull w2p = pk2(w2, w2);
                float m0a = -3.402823466e+38f, m1a = m0a;
                float m0b = m0a, m1b = m0a;
#pragma unroll
                for (int i = 0; i < 10; i++) {
                    {
                        ull acc = mul2(w2p, xe[i + 1]);
                        acc = fma2(wa.y, xo[i], acc);
                        acc = fma2(wa.x, xe[i], acc);
                        const float2 y = upk2(acc);
                        m0a = fmaxf(m0a, y.x);
                        m1a = fmaxf(m1a, y.y);
                    }
                    if (i < 9) {
                        ull acc = mul2(w2p, xe[i + 11]);
                        acc = fma2(wa.y, xo[i + 10], acc);
                        acc = fma2(wa.x, xe[i + 10], acc);
                        const float2 y = upk2(acc);
                        m0b = fmaxf(m0b, y.x);
                        m1b = fmaxf(m1b, y.y);
                    }
                }
                stg_w[lane * 30 + f] =
                    fmaxf(fmaxf(m0a, m1a), fmaxf(m0b, m1b));

                wa = wan;
                w2 = w2n;
            }
        }

        // glove store: DRAM latency absorbed by the filter loop above
        if (lane < 25)
            reinterpret_cast<float4*>(out)[(size_t)p * 250 + 225 + lane] = gval;

        __syncwarp();

        // ---- coalesced store: 900 floats as float4, bias added here ----
        {
            float* outp = out + (size_t)p * 1000;
#pragma unroll
            for (int it = 0; it < 8; it++) {
                const int j4 = it * 32 + lane;          // float4 index, 225 total
                if (j4 < 225) {
                    const float4 v = reinterpret_cast<const float4*>(stg_w)[j4];
                    const float4 b = __ldg(reinterpret_cast<const float4*>(conv_b) + j4);
                    float4 r;
                    r.x = v.x + b.x; r.y = v.y + b.y;
                    r.z = v.z + b.z; r.w = v.w + b.w;
                    reinterpret_cast<float4*>(outp)[j4] = r;
                }
            }
        }
        __syncwarp();

        if (pn >= n_pos) break;
        p = pn;
        c = cn;
    }
}

extern "C" void kernel_launch(void* const* d_in, const int* in_sizes, int n_in,
                              void* d_out, int out_size)
{
    const int*   char_ids = (const int*)d_in[0];
    const int*   word_ids = (const int*)d_in[1];
    const float* char_emb = (const float*)d_in[2];
    const float* conv_w   = (const float*)d_in[3];
    const float* conv_b   = (const float*)d_in[4];
    const float* glove    = (const float*)d_in[5];
    float*       out      = (float*)d_out;

    const int n_pos = in_sizes[1];   // B*S

    int blocks = 592;                // 4 resident blocks/SM on 148 SMs
    if (blocks * (TH / 32) > n_pos) blocks = (n_pos + TH / 32 - 1) / (TH / 32);
    encoder_kernel<<<blocks, TH>>>(char_ids, word_ids, char_emb, conv_w, conv_b,
                                   (const float4*)glove, out, n_pos);
}

// round 15
// speedup vs baseline: 1.1551x; 1.0123x over previous
#include <cuda_runtime.h>
#include <cstdint>

#define CHAR_EMB 30
#define NFILT    30
#define MAXW     40
#define NCHARS   102
#define TH       128          // 4 warps/block, one position per warp
#define FB       5            // filters interleaved per block

typedef unsigned long long ull;

union F2U { float2 f; ull u; };

__device__ __forceinline__ ull pk2(float lo, float hi) {
    F2U v; v.f = make_float2(lo, hi); return v.u;
}
__device__ __forceinline__ float2 upk2(ull x) {
    F2U v; v.u = x; return v.f;
}
__device__ __forceinline__ ull fma2(ull a, ull b, ull c) {
    ull d;
    asm("fma.rn.f32x2 %0, %1, %2, %3;" : "=l"(d) : "l"(a), "l"(b), "l"(c));
    return d;
}
__device__ __forceinline__ ull mul2(ull a, ull b) {
    ull d;
    asm("mul.rn.f32x2 %0, %1, %2;" : "=l"(d) : "l"(a), "l"(b));
    return d;
}

// R14 skeleton with the filter loop restructured into blocks of 5 filters
// processed simultaneously: per time-step the body issues 15 independent
// FMA2 + 10 independent FMNMX -> ~5x wider per-warp ILP window.
__global__ __launch_bounds__(TH, 3)
void encoder_kernel(const int*    __restrict__ char_ids,
                    const int*    __restrict__ word_ids,
                    const float*  __restrict__ char_emb,
                    const float*  __restrict__ conv_w,
                    const float*  __restrict__ conv_b,
                    const float4* __restrict__ glove4,
                    float*        __restrict__ out,
                    int n_pos)
{
    __shared__ float      emb_s[NCHARS * CHAR_EMB];  // [char][e]
    __shared__ ulonglong2 wsA[900];                  // [f*30+e] = {w0pair, w1pair}
    __shared__ float      wsW2[900];                 // [f*30+e] = w2
    __shared__ float      stg[4][900];               // per-warp output stage

    const int tid  = threadIdx.x;
    const int lane = tid & 31;
    const int wrp  = tid >> 5;

    for (int i = tid; i < NCHARS * CHAR_EMB; i += TH)
        emb_s[i] = char_emb[i];
    for (int oc = tid; oc < 900; oc += TH) {
        const int e = oc / NFILT, f = oc % NFILT;
        const float* wp = conv_w + (size_t)oc * 3;
        ulonglong2 a;
        a.x = pk2(wp[0], wp[0]);
        a.y = pk2(wp[1], wp[1]);
        wsA[f * 30 + e]  = a;
        wsW2[f * 30 + e] = wp[2];
    }
    __syncthreads();

    const int el = (lane < CHAR_EMB) ? lane : CHAR_EMB - 1;  // safe column
    float* stg_w = stg[wrp];

    const int wstride = gridDim.x * (TH / 32);
    int p = blockIdx.x * (TH / 32) + wrp;
    if (p >= n_pos) return;

    int2 c = make_int2(0, 0);
    if (lane < 20) c = reinterpret_cast<const int2*>(char_ids)[(size_t)p * 20 + lane];

    while (true) {
        const int pn = p + wstride;
        int2 cn = make_int2(0, 0);
        if (pn < n_pos && lane < 20)
            cn = reinterpret_cast<const int2*>(char_ids)[(size_t)pn * 20 + lane];

        // glove: random-DRAM load issued early, stored after the filter loop
        float4 gval = make_float4(0.f, 0.f, 0.f, 0.f);
        if (lane < 25) {
            const int wid = word_ids[p];
            gval = __ldg(glove4 + (size_t)wid * 25 + lane);
        }

        // ---- gather + pack x[e = lane, 0..39] into both conv phases ----
        ull xe[20], xo[19];
        {
#define EV(t) emb_s[__shfl_sync(0xFFFFFFFFu, (((t) & 1) ? c.y : c.x), (t) >> 1) * CHAR_EMB + el]
            float x0 = EV(0);
            float x1 = EV(1);
            xe[0] = pk2(x0, x1);
#pragma unroll
            for (int i = 1; i < 20; i++) {
                float x2 = EV(2 * i);
                float x3 = EV(2 * i + 1);
                xe[i]     = pk2(x2, x3);
                xo[i - 1] = pk2(x1, x2);
                x1 = x3;
            }
#undef EV
        }

        // ---- 6 blocks of 5 filters, interleaved for wide ILP ----
        if (lane < CHAR_EMB) {
#pragma unroll 1
            for (int fb = 0; fb < NFILT; fb += FB) {
                ull W0[FB], W1[FB], W2[FB];
                float M0[FB], M1[FB];
#pragma unroll
                for (int j = 0; j < FB; j++) {
                    const ulonglong2 wa = wsA[(fb + j) * 30 + lane];
                    const float      w2 = wsW2[(fb + j) * 30 + lane];
                    W0[j] = wa.x;
                    W1[j] = wa.y;
                    W2[j] = pk2(w2, w2);
                    M0[j] = -3.402823466e+38f;
                    M1[j] = M0[j];
                }
#pragma unroll
                for (int i = 0; i < 19; i++) {
#pragma unroll
                    for (int j = 0; j < FB; j++) {
                        ull acc = mul2(W2[j], xe[i + 1]);
                        acc = fma2(W1[j], xo[i], acc);
                        acc = fma2(W0[j], xe[i], acc);
                        const float2 y = upk2(acc);
                        M0[j] = fmaxf(M0[j], y.x);
                        M1[j] = fmaxf(M1[j], y.y);
                    }
                }
#pragma unroll
                for (int j = 0; j < FB; j++)
                    stg_w[lane * 30 + fb + j] = fmaxf(M0[j], M1[j]);
            }
        }

        // glove store: latency fully absorbed by the filter loop above
        if (lane < 25)
            reinterpret_cast<float4*>(out)[(size_t)p * 250 + 225 + lane] = gval;

        __syncwarp();

        // ---- coalesced store: 900 floats as float4, bias added here ----
        {
            float* outp = out + (size_t)p * 1000;
#pragma unroll
            for (int it = 0; it < 8; it++) {
                const int j4 = it * 32 + lane;          // float4 index, 225 total
                if (j4 < 225) {
                    const float4 v = reinterpret_cast<const float4*>(stg_w)[j4];
                    const float4 b = __ldg(reinterpret_cast<const float4*>(conv_b) + j4);
                    float4 r;
                    r.x = v.x + b.x; r.y = v.y + b.y;
                    r.z = v.z + b.z; r.w = v.w + b.w;
                    reinterpret_cast<float4*>(outp)[j4] = r;
                }
            }
        }
        __syncwarp();

        if (pn >= n_pos) break;
        p = pn;
        c = cn;
    }
}

extern "C" void kernel_launch(void* const* d_in, const int* in_sizes, int n_in,
                              void* d_out, int out_size)
{
    const int*   char_ids = (const int*)d_in[0];
    const int*   word_ids = (const int*)d_in[1];
    const float* char_emb = (const float*)d_in[2];
    const float* conv_w   = (const float*)d_in[3];
    const float* conv_b   = (const float*)d_in[4];
    const float* glove    = (const float*)d_in[5];
    float*       out      = (float*)d_out;

    const int n_pos = in_sizes[1];   // B*S

    int blocks = 444;                // 3 resident blocks/SM on 148 SMs
    if (blocks * (TH / 32) > n_pos) blocks = (n_pos + TH / 32 - 1) / (TH / 32);
    encoder_kernel<<<blocks, TH>>>(char_ids, word_ids, char_emb, conv_w, conv_b,
                                   (const float4*)glove, out, n_pos);
}